// round 14
// baseline (speedup 1.0000x reference)
#include <cuda_runtime.h>
#include <cstdint>

// ---------------- problem constants ----------------
#define BATCH   2
#define T_SEQ   2048
#define C_DIM   1024
#define NH      16
#define HD      64
#define E_NUM   8
#define HID_DIM 4096
#define TOPK    2
#define N_TOK   (BATCH * T_SEQ)        // 4096
#define NSLOT   (N_TOK * TOPK)         // 8192

// ---------------- static scratch (device globals; no allocations) ----------------
__device__ float g_h   [N_TOK * C_DIM];        // rmsnorm output (reused for h2)
__device__ float g_q   [N_TOK * C_DIM];
__device__ float g_kv  [N_TOK * 2 * C_DIM];
__device__ float g_y   [N_TOK * C_DIM];
__device__ float g_x2  [N_TOK * C_DIM];        // after attention residual
__device__ float g_xg  [NSLOT * C_DIM];        // gathered tokens per expert
__device__ float g_gate[NSLOT * HID_DIM];
__device__ float g_up  [NSLOT * HID_DIM];
__device__ float g_dwn [NSLOT * C_DIM];
__device__ int   g_sel [N_TOK * TOPK];
__device__ float g_rwt [N_TOK * TOPK];
__device__ int   g_cnt [E_NUM];
__device__ int   g_off [E_NUM];
__device__ int   g_fill[E_NUM];
__device__ int   g_slot[N_TOK * TOPK];
__device__ int   g_tok [NSLOT];

// ---------------- RMSNorm ----------------
__device__ __forceinline__ void rms_body(const float* __restrict__ in,
                                         const float* __restrict__ w,
                                         float* __restrict__ outp) {
    int row = blockIdx.x;
    const float* xr = in + (size_t)row * C_DIM;
    float ss = 0.f;
    for (int c = threadIdx.x; c < C_DIM; c += 256) { float v = xr[c]; ss += v * v; }
    __shared__ float sh[8];
    #pragma unroll
    for (int o = 16; o; o >>= 1) ss += __shfl_xor_sync(0xffffffffu, ss, o);
    int wid = threadIdx.x >> 5;
    if ((threadIdx.x & 31) == 0) sh[wid] = ss;
    __syncthreads();
    if (threadIdx.x < 32) {
        float v = (threadIdx.x < 8) ? sh[threadIdx.x] : 0.f;
        #pragma unroll
        for (int o = 4; o; o >>= 1) v += __shfl_xor_sync(0xffffffffu, v, o);
        if (threadIdx.x == 0) sh[0] = v;
    }
    __syncthreads();
    float scale = rsqrtf(sh[0] * (1.f / (float)C_DIM) + 1e-8f);
    for (int c = threadIdx.x; c < C_DIM; c += 256)
        outp[(size_t)row * C_DIM + c] = xr[c] * scale * w[c];
}

__global__ void __launch_bounds__(256) k_rms1(const float* __restrict__ x,
                                              const float* __restrict__ w) {
    rms_body(x, w, g_h);
}
__global__ void __launch_bounds__(256) k_rms2(const float* __restrict__ w) {
    rms_body(g_x2, w, g_h);
}

// ---------------- SGEMM core: 128x128x8, 256 threads, 8x8 microtile ----------------
template<bool HAS_BIAS, bool HAS_RES>
__device__ __forceinline__ void sgemm_body(
    int M, int N, int K,
    const float* __restrict__ A, const float* __restrict__ B,
    const float* __restrict__ bias, const float* __restrict__ res,
    float* __restrict__ C, int mtile, int ntile) {
    constexpr int BM = 128, BN = 128, BK = 8, TM = 8, TN = 8;
    __shared__ float As[BK][BM];
    __shared__ float Bs[BK][BN];
    const int tid  = threadIdx.x;
    const int aRow = tid >> 1;
    const int aCol = (tid & 1) << 2;
    const int bRow = tid >> 5;
    const int bCol = (tid & 31) << 2;
    const int tRow = (tid >> 4) << 3;
    const int tCol = (tid & 15) << 3;

    const float* Ablk = A + (size_t)mtile * BM * K;
    const float* Bblk = B + (size_t)ntile * BN;
    const bool aValid = (mtile * BM + aRow) < M;

    float acc[TM][TN];
    #pragma unroll
    for (int i = 0; i < TM; i++)
        #pragma unroll
        for (int j = 0; j < TN; j++) acc[i][j] = 0.f;

    for (int k0 = 0; k0 < K; k0 += BK) {
        float4 av = aValid ? *(const float4*)(Ablk + (size_t)aRow * K + k0 + aCol)
                           : make_float4(0.f, 0.f, 0.f, 0.f);
        As[aCol + 0][aRow] = av.x;
        As[aCol + 1][aRow] = av.y;
        As[aCol + 2][aRow] = av.z;
        As[aCol + 3][aRow] = av.w;
        *(float4*)&Bs[bRow][bCol] = *(const float4*)(Bblk + (size_t)(k0 + bRow) * N + bCol);
        __syncthreads();
        #pragma unroll
        for (int k = 0; k < BK; k++) {
            float regM[TM], regN[TN];
            #pragma unroll
            for (int i = 0; i < TM; i++) regM[i] = As[k][tRow + i];
            #pragma unroll
            for (int j = 0; j < TN; j++) regN[j] = Bs[k][tCol + j];
            #pragma unroll
            for (int i = 0; i < TM; i++)
                #pragma unroll
                for (int j = 0; j < TN; j++) acc[i][j] += regM[i] * regN[j];
        }
        __syncthreads();
    }
    #pragma unroll
    for (int i = 0; i < TM; i++) {
        int gr = mtile * BM + tRow + i;
        if (gr >= M) continue;
        float* Cp = C + (size_t)gr * N + (size_t)ntile * BN + tCol;
        const float* Rp = HAS_RES ? (res + (size_t)gr * N + (size_t)ntile * BN + tCol) : nullptr;
        #pragma unroll
        for (int j = 0; j < TN; j++) {
            float v = acc[i][j];
            if (HAS_BIAS) v += bias[(size_t)ntile * BN + tCol + j];
            if (HAS_RES)  v += Rp[j];
            Cp[j] = v;
        }
    }
}

__global__ void __launch_bounds__(256) k_gemm_q(const float* __restrict__ qw,
                                                const float* __restrict__ qb) {
    sgemm_body<true, false>(N_TOK, C_DIM, C_DIM, g_h, qw, qb, nullptr, g_q,
                            blockIdx.y, blockIdx.x);
}
__global__ void __launch_bounds__(256) k_gemm_kv(const float* __restrict__ kvw,
                                                 const float* __restrict__ kvb) {
    sgemm_body<true, false>(N_TOK, 2 * C_DIM, C_DIM, g_h, kvw, kvb, nullptr, g_kv,
                            blockIdx.y, blockIdx.x);
}
__global__ void __launch_bounds__(256) k_gemm_o(const float* __restrict__ ow,
                                                const float* __restrict__ ob,
                                                const float* __restrict__ x) {
    sgemm_body<true, true>(N_TOK, C_DIM, C_DIM, g_y, ow, ob, x, g_x2,
                           blockIdx.y, blockIdx.x);
}

// ---------------- grouped MoE GEMM ----------------
__device__ __forceinline__ void moe_body(const float* __restrict__ Aall,
                                         const float* __restrict__ Ball,
                                         float* __restrict__ Call, int N, int K) {
    int e = blockIdx.z;
    int Me = g_cnt[e];
    int mtile = blockIdx.y;
    if (mtile * 128 >= Me) return;
    int base = g_off[e];
    sgemm_body<false, false>(Me, N, K,
                             Aall + (size_t)base * K,
                             Ball + (size_t)e * K * N,
                             nullptr, nullptr,
                             Call + (size_t)base * N,
                             mtile, blockIdx.x);
}

__global__ void __launch_bounds__(256) k_moe_gate(const float* __restrict__ gw) {
    moe_body(g_xg, gw, g_gate, HID_DIM, C_DIM);
}
__global__ void __launch_bounds__(256) k_moe_up(const float* __restrict__ uw) {
    moe_body(g_xg, uw, g_up, HID_DIM, C_DIM);
}
__global__ void __launch_bounds__(256) k_moe_down(const float* __restrict__ dw) {
    moe_body(g_gate, dw, g_dwn, C_DIM, HID_DIM);
}

// ---------------- attention: flash-style, ALiBi, causal ----------------
__global__ void __launch_bounds__(64) k_attn() {
    const int qt = blockIdx.x;   // query tile (64 queries)
    const int h  = blockIdx.y;
    const int b  = blockIdx.z;
    const int tid = threadIdx.x; // one query row per thread
    __shared__ float Ks[64][64];
    __shared__ float Vs[64][64];
    const int qpos = qt * 64 + tid;
    const float slope = (float)(h + 1) * (1.0f / (float)NH);

    float qreg[HD], o[HD];
    {
        const float* qr = g_q + (size_t)(b * T_SEQ + qpos) * C_DIM + h * HD;
        #pragma unroll
        for (int d = 0; d < HD; d++) { qreg[d] = qr[d] * 0.125f; o[d] = 0.f; }
    }
    float m = -1e30f, l = 0.f;

    for (int kt = 0; kt <= qt; kt++) {
        __syncthreads();
        const float* kb = g_kv + (size_t)(b * T_SEQ + kt * 64) * (2 * C_DIM) + h * HD;
        #pragma unroll 4
        for (int i = 0; i < 64; i++) {
            Ks[i][tid] = kb[(size_t)i * (2 * C_DIM) + tid];
            Vs[i][tid] = kb[(size_t)i * (2 * C_DIM) + C_DIM + tid];
        }
        __syncthreads();
        const int nvalid = (kt < qt) ? 64 : (tid + 1);
        const float bias0 = slope * (float)(kt * 64 - qpos);

        for (int j0 = 0; j0 < nvalid; j0 += 16) {
            float s[16];
            float cmax = -1e30f;
            #pragma unroll
            for (int jj = 0; jj < 16; jj++) {
                int j = j0 + jj;
                float s0 = 0.f, s1 = 0.f, s2 = 0.f, s3 = 0.f;
                #pragma unroll
                for (int d = 0; d < HD; d += 16) {
                    float4 a0 = *(const float4*)&Ks[j][d];
                    float4 a1 = *(const float4*)&Ks[j][d + 4];
                    float4 a2 = *(const float4*)&Ks[j][d + 8];
                    float4 a3 = *(const float4*)&Ks[j][d + 12];
                    s0 += qreg[d+0]*a0.x + qreg[d+1]*a0.y + qreg[d+2]*a0.z + qreg[d+3]*a0.w;
                    s1 += qreg[d+4]*a1.x + qreg[d+5]*a1.y + qreg[d+6]*a1.z + qreg[d+7]*a1.w;
                    s2 += qreg[d+8]*a2.x + qreg[d+9]*a2.y + qreg[d+10]*a2.z + qreg[d+11]*a2.w;
                    s3 += qreg[d+12]*a3.x + qreg[d+13]*a3.y + qreg[d+14]*a3.z + qreg[d+15]*a3.w;
                }
                float v = (s0 + s1) + (s2 + s3) + bias0 + slope * (float)j;
                if (j >= nvalid) v = -1e30f;     // masked: exp() -> 0, Vs row is finite
                s[jj] = v;
                cmax = fmaxf(cmax, v);
            }
            float mnew = fmaxf(m, cmax);
            float corr = __expf(m - mnew);
            m = mnew;
            l *= corr;
            #pragma unroll
            for (int d = 0; d < HD; d++) o[d] *= corr;
            #pragma unroll
            for (int jj = 0; jj < 16; jj++) {
                int j = j0 + jj;
                float p = __expf(s[jj] - m);
                l += p;
                #pragma unroll
                for (int d = 0; d < HD; d += 4) {
                    float4 v4 = *(const float4*)&Vs[j][d];
                    o[d+0] += p * v4.x; o[d+1] += p * v4.y;
                    o[d+2] += p * v4.z; o[d+3] += p * v4.w;
                }
            }
        }
    }
    float inv = 1.f / l;
    float* yr = g_y + (size_t)(b * T_SEQ + qpos) * C_DIM + h * HD;
    #pragma unroll
    for (int d = 0; d < HD; d++) yr[d] = o[d] * inv;
}

// ---------------- router + top-2 ----------------
__global__ void __launch_bounds__(256) k_router(const float* __restrict__ rw) {
    int warp = (blockIdx.x * blockDim.x + threadIdx.x) >> 5;
    int lane = threadIdx.x & 31;
    if (warp >= N_TOK) return;
    float acc[E_NUM];
    #pragma unroll
    for (int e = 0; e < E_NUM; e++) acc[e] = 0.f;
    const float* hr = g_h + (size_t)warp * C_DIM;
    for (int c = lane; c < C_DIM; c += 32) {
        float hv = hr[c];
        #pragma unroll
        for (int e = 0; e < E_NUM; e++) acc[e] += hv * rw[(size_t)c * E_NUM + e];
    }
    #pragma unroll
    for (int e = 0; e < E_NUM; e++)
        #pragma unroll
        for (int o = 16; o; o >>= 1) acc[e] += __shfl_xor_sync(0xffffffffu, acc[e], o);
    if (lane == 0) {
        int i0 = 0; float m0 = acc[0];
        #pragma unroll
        for (int e = 1; e < E_NUM; e++) if (acc[e] > m0) { m0 = acc[e]; i0 = e; }
        int i1 = -1; float m1 = -1e30f;
        #pragma unroll
        for (int e = 0; e < E_NUM; e++)
            if (e != i0 && acc[e] > m1) { m1 = acc[e]; i1 = e; }
        float e1 = __expf(m1 - m0);
        float denom = 1.f + e1;
        g_sel[2 * warp]     = i0;
        g_sel[2 * warp + 1] = i1;
        g_rwt[2 * warp]     = 1.f / denom;
        g_rwt[2 * warp + 1] = e1 / denom;
    }
}

// ---------------- routing bookkeeping ----------------
__global__ void k_zero() {
    if (threadIdx.x < E_NUM) { g_cnt[threadIdx.x] = 0; g_fill[threadIdx.x] = 0; }
}
__global__ void __launch_bounds__(256) k_count() {
    int t = blockIdx.x * blockDim.x + threadIdx.x;
    if (t < N_TOK) {
        atomicAdd(&g_cnt[g_sel[2 * t]], 1);
        atomicAdd(&g_cnt[g_sel[2 * t + 1]], 1);
    }
}
__global__ void k_offsets() {
    int s = 0;
    for (int e = 0; e < E_NUM; e++) { g_off[e] = s; s += g_cnt[e]; }
}
__global__ void __launch_bounds__(256) k_scatter() {
    int t = blockIdx.x * blockDim.x + threadIdx.x;
    if (t < N_TOK) {
        #pragma unroll
        for (int k = 0; k < TOPK; k++) {
            int e = g_sel[2 * t + k];
            int pos = atomicAdd(&g_fill[e], 1);
            int slot = g_off[e] + pos;
            g_tok[slot] = t;
            g_slot[2 * t + k] = slot;
        }
    }
}
__global__ void __launch_bounds__(256) k_gather() {
    int slot = blockIdx.x;
    int t = g_tok[slot];
    const float* src = g_h + (size_t)t * C_DIM;
    float* dst = g_xg + (size_t)slot * C_DIM;
    for (int c = threadIdx.x; c < C_DIM; c += 256) dst[c] = src[c];
}

// ---------------- SiLU(gate) * up ----------------
__global__ void __launch_bounds__(256) k_silu() {
    size_t i = (size_t)blockIdx.x * blockDim.x + threadIdx.x;
    float g = g_gate[i];
    float u = g_up[i];
    g_gate[i] = g / (1.f + __expf(-g)) * u;
}

// ---------------- combine: out = x2 + w0*dwn[s0] + w1*dwn[s1] ----------------
__global__ void __launch_bounds__(256) k_combine(float* __restrict__ out) {
    int t = blockIdx.x;
    int s0 = g_slot[2 * t], s1 = g_slot[2 * t + 1];
    float w0 = g_rwt[2 * t], w1 = g_rwt[2 * t + 1];
    const float* xr = g_x2 + (size_t)t * C_DIM;
    const float* d0 = g_dwn + (size_t)s0 * C_DIM;
    const float* d1 = g_dwn + (size_t)s1 * C_DIM;
    float* op = out + (size_t)t * C_DIM;
    for (int c = threadIdx.x; c < C_DIM; c += 256)
        op[c] = xr[c] + w0 * d0[c] + w1 * d1[c];
}

// ---------------- launch ----------------
extern "C" void kernel_launch(void* const* d_in, const int* in_sizes, int n_in,
                              void* d_out, int out_size) {
    const float* x   = (const float*)d_in[0];
    const float* anw = (const float*)d_in[1];
    const float* fnw = (const float*)d_in[2];
    const float* qw  = (const float*)d_in[3];
    const float* qb  = (const float*)d_in[4];
    const float* kvw = (const float*)d_in[5];
    const float* kvb = (const float*)d_in[6];
    const float* ow  = (const float*)d_in[7];
    const float* ob  = (const float*)d_in[8];
    const float* rw  = (const float*)d_in[9];
    const float* gw  = (const float*)d_in[10];
    const float* uw  = (const float*)d_in[11];
    const float* dw  = (const float*)d_in[12];
    float* out = (float*)d_out;

    // attention path
    k_rms1<<<N_TOK, 256>>>(x, anw);
    k_gemm_q <<<dim3(C_DIM / 128, N_TOK / 128), 256>>>(qw, qb);
    k_gemm_kv<<<dim3(2 * C_DIM / 128, N_TOK / 128), 256>>>(kvw, kvb);
    k_attn<<<dim3(T_SEQ / 64, NH, BATCH), 64>>>();
    k_gemm_o <<<dim3(C_DIM / 128, N_TOK / 128), 256>>>(ow, ob, x);

    // MoE path
    k_rms2<<<N_TOK, 256>>>(fnw);
    k_zero<<<1, 32>>>();
    k_router<<<(N_TOK * 32) / 256, 256>>>(rw);
    k_count<<<N_TOK / 256, 256>>>();
    k_offsets<<<1, 1>>>();
    k_scatter<<<N_TOK / 256, 256>>>();
    k_gather<<<NSLOT, 256>>>();
    k_moe_gate<<<dim3(HID_DIM / 128, NSLOT / 128, E_NUM), 256>>>(gw);
    k_moe_up  <<<dim3(HID_DIM / 128, NSLOT / 128, E_NUM), 256>>>(uw);
    k_silu<<<(NSLOT * HID_DIM) / 256, 256>>>();
    k_moe_down<<<dim3(C_DIM / 128, NSLOT / 128, E_NUM), 256>>>(dw);
    k_combine<<<N_TOK, 256>>>(out);
}

// round 15
// speedup vs baseline: 1.0005x; 1.0005x over previous
#include <cuda_runtime.h>
#include <cstdint>

// ---------------- problem constants ----------------
#define BATCH   2
#define T_SEQ   2048
#define C_DIM   1024
#define NH      16
#define HD      64
#define E_NUM   8
#define HID_DIM 4096
#define TOPK    2
#define N_TOK   (BATCH * T_SEQ)        // 4096
#define NSLOT   (N_TOK * TOPK)         // 8192

// ---------------- static scratch (device globals; no allocations) ----------------
__device__ float g_h   [N_TOK * C_DIM];        // rmsnorm output (reused for h2)
__device__ float g_q   [N_TOK * C_DIM];
__device__ float g_kv  [N_TOK * 2 * C_DIM];
__device__ float g_y   [N_TOK * C_DIM];
__device__ float g_x2  [N_TOK * C_DIM];        // after attention residual
__device__ float g_xg  [NSLOT * C_DIM];        // gathered tokens per expert
__device__ float g_gate[NSLOT * HID_DIM];
__device__ float g_up  [NSLOT * HID_DIM];
__device__ float g_dwn [NSLOT * C_DIM];
__device__ int   g_sel [N_TOK * TOPK];
__device__ float g_rwt [N_TOK * TOPK];
__device__ int   g_cnt [E_NUM];
__device__ int   g_off [E_NUM];
__device__ int   g_fill[E_NUM];
__device__ int   g_slot[N_TOK * TOPK];
__device__ int   g_tok [NSLOT];

// ---------------- RMSNorm ----------------
__device__ __forceinline__ void rms_body(const float* __restrict__ in,
                                         const float* __restrict__ w,
                                         float* __restrict__ outp) {
    int row = blockIdx.x;
    const float* xr = in + (size_t)row * C_DIM;
    float ss = 0.f;
    for (int c = threadIdx.x; c < C_DIM; c += 256) { float v = xr[c]; ss += v * v; }
    __shared__ float sh[8];
    #pragma unroll
    for (int o = 16; o; o >>= 1) ss += __shfl_xor_sync(0xffffffffu, ss, o);
    int wid = threadIdx.x >> 5;
    if ((threadIdx.x & 31) == 0) sh[wid] = ss;
    __syncthreads();
    if (threadIdx.x < 32) {
        float v = (threadIdx.x < 8) ? sh[threadIdx.x] : 0.f;
        #pragma unroll
        for (int o = 4; o; o >>= 1) v += __shfl_xor_sync(0xffffffffu, v, o);
        if (threadIdx.x == 0) sh[0] = v;
    }
    __syncthreads();
    float scale = rsqrtf(sh[0] * (1.f / (float)C_DIM) + 1e-8f);
    for (int c = threadIdx.x; c < C_DIM; c += 256)
        outp[(size_t)row * C_DIM + c] = xr[c] * scale * w[c];
}

__global__ void __launch_bounds__(256) k_rms1(const float* __restrict__ x,
                                              const float* __restrict__ w) {
    rms_body(x, w, g_h);
}
__global__ void __launch_bounds__(256) k_rms2(const float* __restrict__ w) {
    rms_body(g_x2, w, g_h);
}

// ---------------- SGEMM core: 128x128x8, 256 threads, 8x8 microtile ----------------
template<bool HAS_BIAS, bool HAS_RES>
__device__ __forceinline__ void sgemm_body(
    int M, int N, int K,
    const float* __restrict__ A, const float* __restrict__ B,
    const float* __restrict__ bias, const float* __restrict__ res,
    float* __restrict__ C, int mtile, int ntile) {
    constexpr int BM = 128, BN = 128, BK = 8, TM = 8, TN = 8;
    __shared__ float As[BK][BM];
    __shared__ float Bs[BK][BN];
    const int tid  = threadIdx.x;
    const int aRow = tid >> 1;
    const int aCol = (tid & 1) << 2;
    const int bRow = tid >> 5;
    const int bCol = (tid & 31) << 2;
    const int tRow = (tid >> 4) << 3;
    const int tCol = (tid & 15) << 3;

    const float* Ablk = A + (size_t)mtile * BM * K;
    const float* Bblk = B + (size_t)ntile * BN;
    const bool aValid = (mtile * BM + aRow) < M;

    float acc[TM][TN];
    #pragma unroll
    for (int i = 0; i < TM; i++)
        #pragma unroll
        for (int j = 0; j < TN; j++) acc[i][j] = 0.f;

    for (int k0 = 0; k0 < K; k0 += BK) {
        float4 av = aValid ? *(const float4*)(Ablk + (size_t)aRow * K + k0 + aCol)
                           : make_float4(0.f, 0.f, 0.f, 0.f);
        As[aCol + 0][aRow] = av.x;
        As[aCol + 1][aRow] = av.y;
        As[aCol + 2][aRow] = av.z;
        As[aCol + 3][aRow] = av.w;
        *(float4*)&Bs[bRow][bCol] = *(const float4*)(Bblk + (size_t)(k0 + bRow) * N + bCol);
        __syncthreads();
        #pragma unroll
        for (int k = 0; k < BK; k++) {
            float regM[TM], regN[TN];
            #pragma unroll
            for (int i = 0; i < TM; i++) regM[i] = As[k][tRow + i];
            #pragma unroll
            for (int j = 0; j < TN; j++) regN[j] = Bs[k][tCol + j];
            #pragma unroll
            for (int i = 0; i < TM; i++)
                #pragma unroll
                for (int j = 0; j < TN; j++) acc[i][j] += regM[i] * regN[j];
        }
        __syncthreads();
    }
    #pragma unroll
    for (int i = 0; i < TM; i++) {
        int gr = mtile * BM + tRow + i;
        if (gr >= M) continue;
        float* Cp = C + (size_t)gr * N + (size_t)ntile * BN + tCol;
        const float* Rp = HAS_RES ? (res + (size_t)gr * N + (size_t)ntile * BN + tCol) : nullptr;
        #pragma unroll
        for (int j = 0; j < TN; j++) {
            float v = acc[i][j];
            if (HAS_BIAS) v += bias[(size_t)ntile * BN + tCol + j];
            if (HAS_RES)  v += Rp[j];
            Cp[j] = v;
        }
    }
}

__global__ void __launch_bounds__(256) k_gemm_q(const float* __restrict__ qw,
                                                const float* __restrict__ qb) {
    sgemm_body<true, false>(N_TOK, C_DIM, C_DIM, g_h, qw, qb, nullptr, g_q,
                            blockIdx.y, blockIdx.x);
}
__global__ void __launch_bounds__(256) k_gemm_kv(const float* __restrict__ kvw,
                                                 const float* __restrict__ kvb) {
    sgemm_body<true, false>(N_TOK, 2 * C_DIM, C_DIM, g_h, kvw, kvb, nullptr, g_kv,
                            blockIdx.y, blockIdx.x);
}
__global__ void __launch_bounds__(256) k_gemm_o(const float* __restrict__ ow,
                                                const float* __restrict__ ob,
                                                const float* __restrict__ x) {
    sgemm_body<true, true>(N_TOK, C_DIM, C_DIM, g_y, ow, ob, x, g_x2,
                           blockIdx.y, blockIdx.x);
}

// ---------------- grouped MoE GEMM ----------------
__device__ __forceinline__ void moe_body(const float* __restrict__ Aall,
                                         const float* __restrict__ Ball,
                                         float* __restrict__ Call, int N, int K) {
    int e = blockIdx.z;
    int Me = g_cnt[e];
    int mtile = blockIdx.y;
    if (mtile * 128 >= Me) return;
    int base = g_off[e];
    sgemm_body<false, false>(Me, N, K,
                             Aall + (size_t)base * K,
                             Ball + (size_t)e * K * N,
                             nullptr, nullptr,
                             Call + (size_t)base * N,
                             mtile, blockIdx.x);
}

__global__ void __launch_bounds__(256) k_moe_gate(const float* __restrict__ gw) {
    moe_body(g_xg, gw, g_gate, HID_DIM, C_DIM);
}
__global__ void __launch_bounds__(256) k_moe_up(const float* __restrict__ uw) {
    moe_body(g_xg, uw, g_up, HID_DIM, C_DIM);
}
__global__ void __launch_bounds__(256) k_moe_down(const float* __restrict__ dw) {
    moe_body(g_gate, dw, g_dwn, C_DIM, HID_DIM);
}

// ---------------- attention: flash-style, ALiBi, causal ----------------
__global__ void __launch_bounds__(64) k_attn() {
    const int qt = blockIdx.x;   // query tile (64 queries)
    const int h  = blockIdx.y;
    const int b  = blockIdx.z;
    const int tid = threadIdx.x; // one query row per thread
    __shared__ float Ks[64][64];
    __shared__ float Vs[64][64];
    const int qpos = qt * 64 + tid;
    const float slope = (float)(h + 1) * (1.0f / (float)NH);

    float qreg[HD], o[HD];
    {
        const float* qr = g_q + (size_t)(b * T_SEQ + qpos) * C_DIM + h * HD;
        #pragma unroll
        for (int d = 0; d < HD; d++) { qreg[d] = qr[d] * 0.125f; o[d] = 0.f; }
    }
    float m = -1e30f, l = 0.f;

    for (int kt = 0; kt <= qt; kt++) {
        __syncthreads();
        const float* kb = g_kv + (size_t)(b * T_SEQ + kt * 64) * (2 * C_DIM) + h * HD;
        #pragma unroll 4
        for (int i = 0; i < 64; i++) {
            Ks[i][tid] = kb[(size_t)i * (2 * C_DIM) + tid];
            Vs[i][tid] = kb[(size_t)i * (2 * C_DIM) + C_DIM + tid];
        }
        __syncthreads();
        const int nvalid = (kt < qt) ? 64 : (tid + 1);
        const float bias0 = slope * (float)(kt * 64 - qpos);

        for (int j0 = 0; j0 < nvalid; j0 += 16) {
            float s[16];
            float cmax = -1e30f;
            #pragma unroll
            for (int jj = 0; jj < 16; jj++) {
                int j = j0 + jj;
                float s0 = 0.f, s1 = 0.f, s2 = 0.f, s3 = 0.f;
                #pragma unroll
                for (int d = 0; d < HD; d += 16) {
                    float4 a0 = *(const float4*)&Ks[j][d];
                    float4 a1 = *(const float4*)&Ks[j][d + 4];
                    float4 a2 = *(const float4*)&Ks[j][d + 8];
                    float4 a3 = *(const float4*)&Ks[j][d + 12];
                    s0 += qreg[d+0]*a0.x + qreg[d+1]*a0.y + qreg[d+2]*a0.z + qreg[d+3]*a0.w;
                    s1 += qreg[d+4]*a1.x + qreg[d+5]*a1.y + qreg[d+6]*a1.z + qreg[d+7]*a1.w;
                    s2 += qreg[d+8]*a2.x + qreg[d+9]*a2.y + qreg[d+10]*a2.z + qreg[d+11]*a2.w;
                    s3 += qreg[d+12]*a3.x + qreg[d+13]*a3.y + qreg[d+14]*a3.z + qreg[d+15]*a3.w;
                }
                float v = (s0 + s1) + (s2 + s3) + bias0 + slope * (float)j;
                if (j >= nvalid) v = -1e30f;     // masked: exp() -> 0, Vs row is finite
                s[jj] = v;
                cmax = fmaxf(cmax, v);
            }
            float mnew = fmaxf(m, cmax);
            float corr = __expf(m - mnew);
            m = mnew;
            l *= corr;
            #pragma unroll
            for (int d = 0; d < HD; d++) o[d] *= corr;
            #pragma unroll
            for (int jj = 0; jj < 16; jj++) {
                int j = j0 + jj;
                float p = __expf(s[jj] - m);
                l += p;
                #pragma unroll
                for (int d = 0; d < HD; d += 4) {
                    float4 v4 = *(const float4*)&Vs[j][d];
                    o[d+0] += p * v4.x; o[d+1] += p * v4.y;
                    o[d+2] += p * v4.z; o[d+3] += p * v4.w;
                }
            }
        }
    }
    float inv = 1.f / l;
    float* yr = g_y + (size_t)(b * T_SEQ + qpos) * C_DIM + h * HD;
    #pragma unroll
    for (int d = 0; d < HD; d++) yr[d] = o[d] * inv;
}

// ---------------- router + top-2 ----------------
__global__ void __launch_bounds__(256) k_router(const float* __restrict__ rw) {
    int warp = (blockIdx.x * blockDim.x + threadIdx.x) >> 5;
    int lane = threadIdx.x & 31;
    if (warp >= N_TOK) return;
    float acc[E_NUM];
    #pragma unroll
    for (int e = 0; e < E_NUM; e++) acc[e] = 0.f;
    const float* hr = g_h + (size_t)warp * C_DIM;
    for (int c = lane; c < C_DIM; c += 32) {
        float hv = hr[c];
        #pragma unroll
        for (int e = 0; e < E_NUM; e++) acc[e] += hv * rw[(size_t)c * E_NUM + e];
    }
    #pragma unroll
    for (int e = 0; e < E_NUM; e++)
        #pragma unroll
        for (int o = 16; o; o >>= 1) acc[e] += __shfl_xor_sync(0xffffffffu, acc[e], o);
    if (lane == 0) {
        int i0 = 0; float m0 = acc[0];
        #pragma unroll
        for (int e = 1; e < E_NUM; e++) if (acc[e] > m0) { m0 = acc[e]; i0 = e; }
        int i1 = -1; float m1 = -1e30f;
        #pragma unroll
        for (int e = 0; e < E_NUM; e++)
            if (e != i0 && acc[e] > m1) { m1 = acc[e]; i1 = e; }
        float e1 = __expf(m1 - m0);
        float denom = 1.f + e1;
        g_sel[2 * warp]     = i0;
        g_sel[2 * warp + 1] = i1;
        g_rwt[2 * warp]     = 1.f / denom;
        g_rwt[2 * warp + 1] = e1 / denom;
    }
}

// ---------------- routing bookkeeping ----------------
__global__ void k_zero() {
    if (threadIdx.x < E_NUM) { g_cnt[threadIdx.x] = 0; g_fill[threadIdx.x] = 0; }
}
__global__ void __launch_bounds__(256) k_count() {
    int t = blockIdx.x * blockDim.x + threadIdx.x;
    if (t < N_TOK) {
        atomicAdd(&g_cnt[g_sel[2 * t]], 1);
        atomicAdd(&g_cnt[g_sel[2 * t + 1]], 1);
    }
}
__global__ void k_offsets() {
    int s = 0;
    for (int e = 0; e < E_NUM; e++) { g_off[e] = s; s += g_cnt[e]; }
}
__global__ void __launch_bounds__(256) k_scatter() {
    int t = blockIdx.x * blockDim.x + threadIdx.x;
    if (t < N_TOK) {
        #pragma unroll
        for (int k = 0; k < TOPK; k++) {
            int e = g_sel[2 * t + k];
            int pos = atomicAdd(&g_fill[e], 1);
            int slot = g_off[e] + pos;
            g_tok[slot] = t;
            g_slot[2 * t + k] = slot;
        }
    }
}
__global__ void __launch_bounds__(256) k_gather() {
    int slot = blockIdx.x;
    int t = g_tok[slot];
    const float* src = g_h + (size_t)t * C_DIM;
    float* dst = g_xg + (size_t)slot * C_DIM;
    for (int c = threadIdx.x; c < C_DIM; c += 256) dst[c] = src[c];
}

// ---------------- SiLU(gate) * up ----------------
__global__ void __launch_bounds__(256) k_silu() {
    size_t i = (size_t)blockIdx.x * blockDim.x + threadIdx.x;
    float g = g_gate[i];
    float u = g_up[i];
    g_gate[i] = g / (1.f + __expf(-g)) * u;
}

// ---------------- combine: out = x2 + w0*dwn[s0] + w1*dwn[s1] ----------------
__global__ void __launch_bounds__(256) k_combine(float* __restrict__ out) {
    int t = blockIdx.x;
    int s0 = g_slot[2 * t], s1 = g_slot[2 * t + 1];
    float w0 = g_rwt[2 * t], w1 = g_rwt[2 * t + 1];
    const float* xr = g_x2 + (size_t)t * C_DIM;
    const float* d0 = g_dwn + (size_t)s0 * C_DIM;
    const float* d1 = g_dwn + (size_t)s1 * C_DIM;
    float* op = out + (size_t)t * C_DIM;
    for (int c = threadIdx.x; c < C_DIM; c += 256)
        op[c] = xr[c] + w0 * d0[c] + w1 * d1[c];
}

// ---------------- launch ----------------
extern "C" void kernel_launch(void* const* d_in, const int* in_sizes, int n_in,
                              void* d_out, int out_size) {
    const float* x   = (const float*)d_in[0];
    const float* anw = (const float*)d_in[1];
    const float* fnw = (const float*)d_in[2];
    const float* qw  = (const float*)d_in[3];
    const float* qb  = (const float*)d_in[4];
    const float* kvw = (const float*)d_in[5];
    const float* kvb = (const float*)d_in[6];
    const float* ow  = (const float*)d_in[7];
    const float* ob  = (const float*)d_in[8];
    const float* rw  = (const float*)d_in[9];
    const float* gw  = (const float*)d_in[10];
    const float* uw  = (const float*)d_in[11];
    const float* dw  = (const float*)d_in[12];
    float* out = (float*)d_out;

    // attention path
    k_rms1<<<N_TOK, 256>>>(x, anw);
    k_gemm_q <<<dim3(C_DIM / 128, N_TOK / 128), 256>>>(qw, qb);
    k_gemm_kv<<<dim3(2 * C_DIM / 128, N_TOK / 128), 256>>>(kvw, kvb);
    k_attn<<<dim3(T_SEQ / 64, NH, BATCH), 64>>>();
    k_gemm_o <<<dim3(C_DIM / 128, N_TOK / 128), 256>>>(ow, ob, x);

    // MoE path
    k_rms2<<<N_TOK, 256>>>(fnw);
    k_zero<<<1, 32>>>();
    k_router<<<(N_TOK * 32) / 256, 256>>>(rw);
    k_count<<<N_TOK / 256, 256>>>();
    k_offsets<<<1, 1>>>();
    k_scatter<<<N_TOK / 256, 256>>>();
    k_gather<<<NSLOT, 256>>>();
    k_moe_gate<<<dim3(HID_DIM / 128, NSLOT / 128, E_NUM), 256>>>(gw);
    k_moe_up  <<<dim3(HID_DIM / 128, NSLOT / 128, E_NUM), 256>>>(uw);
    k_silu<<<(NSLOT * HID_DIM) / 256, 256>>>();
    k_moe_down<<<dim3(C_DIM / 128, NSLOT / 128, E_NUM), 256>>>(dw);
    k_combine<<<N_TOK, 256>>>(out);
}

// round 16
// speedup vs baseline: 1.0027x; 1.0022x over previous
#include <cuda_runtime.h>
#include <cstdint>

// ---------------- problem constants ----------------
#define BATCH   2
#define T_SEQ   2048
#define C_DIM   1024
#define NH      16
#define HD      64
#define E_NUM   8
#define HID_DIM 4096
#define TOPK    2
#define N_TOK   (BATCH * T_SEQ)        // 4096
#define NSLOT   (N_TOK * TOPK)         // 8192

// ---------------- static scratch (device globals; no allocations) ----------------
__device__ float g_h   [N_TOK * C_DIM];        // rmsnorm output (reused for h2)
__device__ float g_q   [N_TOK * C_DIM];
__device__ float g_kv  [N_TOK * 2 * C_DIM];
__device__ float g_y   [N_TOK * C_DIM];
__device__ float g_x2  [N_TOK * C_DIM];        // after attention residual
__device__ float g_xg  [NSLOT * C_DIM];        // gathered tokens per expert
__device__ float g_gate[NSLOT * HID_DIM];
__device__ float g_up  [NSLOT * HID_DIM];
__device__ float g_dwn [NSLOT * C_DIM];
__device__ int   g_sel [N_TOK * TOPK];
__device__ float g_rwt [N_TOK * TOPK];
__device__ int   g_cnt [E_NUM];
__device__ int   g_off [E_NUM];
__device__ int   g_fill[E_NUM];
__device__ int   g_slot[N_TOK * TOPK];
__device__ int   g_tok [NSLOT];

// ---------------- RMSNorm ----------------
__device__ __forceinline__ void rms_body(const float* __restrict__ in,
                                         const float* __restrict__ w,
                                         float* __restrict__ outp) {
    int row = blockIdx.x;
    const float* xr = in + (size_t)row * C_DIM;
    float ss = 0.f;
    for (int c = threadIdx.x; c < C_DIM; c += 256) { float v = xr[c]; ss += v * v; }
    __shared__ float sh[8];
    #pragma unroll
    for (int o = 16; o; o >>= 1) ss += __shfl_xor_sync(0xffffffffu, ss, o);
    int wid = threadIdx.x >> 5;
    if ((threadIdx.x & 31) == 0) sh[wid] = ss;
    __syncthreads();
    if (threadIdx.x < 32) {
        float v = (threadIdx.x < 8) ? sh[threadIdx.x] : 0.f;
        #pragma unroll
        for (int o = 4; o; o >>= 1) v += __shfl_xor_sync(0xffffffffu, v, o);
        if (threadIdx.x == 0) sh[0] = v;
    }
    __syncthreads();
    float scale = rsqrtf(sh[0] * (1.f / (float)C_DIM) + 1e-8f);
    for (int c = threadIdx.x; c < C_DIM; c += 256)
        outp[(size_t)row * C_DIM + c] = xr[c] * scale * w[c];
}

__global__ void __launch_bounds__(256) k_rms1(const float* __restrict__ x,
                                              const float* __restrict__ w) {
    rms_body(x, w, g_h);
}
__global__ void __launch_bounds__(256) k_rms2(const float* __restrict__ w) {
    rms_body(g_x2, w, g_h);
}

// ---------------- SGEMM core: 128x128x8, 256 threads, 8x8 microtile ----------------
template<bool HAS_BIAS, bool HAS_RES>
__device__ __forceinline__ void sgemm_body(
    int M, int N, int K,
    const float* __restrict__ A, const float* __restrict__ B,
    const float* __restrict__ bias, const float* __restrict__ res,
    float* __restrict__ C, int mtile, int ntile) {
    constexpr int BM = 128, BN = 128, BK = 8, TM = 8, TN = 8;
    __shared__ float As[BK][BM];
    __shared__ float Bs[BK][BN];
    const int tid  = threadIdx.x;
    const int aRow = tid >> 1;
    const int aCol = (tid & 1) << 2;
    const int bRow = tid >> 5;
    const int bCol = (tid & 31) << 2;
    const int tRow = (tid >> 4) << 3;
    const int tCol = (tid & 15) << 3;

    const float* Ablk = A + (size_t)mtile * BM * K;
    const float* Bblk = B + (size_t)ntile * BN;
    const bool aValid = (mtile * BM + aRow) < M;

    float acc[TM][TN];
    #pragma unroll
    for (int i = 0; i < TM; i++)
        #pragma unroll
        for (int j = 0; j < TN; j++) acc[i][j] = 0.f;

    for (int k0 = 0; k0 < K; k0 += BK) {
        float4 av = aValid ? *(const float4*)(Ablk + (size_t)aRow * K + k0 + aCol)
                           : make_float4(0.f, 0.f, 0.f, 0.f);
        As[aCol + 0][aRow] = av.x;
        As[aCol + 1][aRow] = av.y;
        As[aCol + 2][aRow] = av.z;
        As[aCol + 3][aRow] = av.w;
        *(float4*)&Bs[bRow][bCol] = *(const float4*)(Bblk + (size_t)(k0 + bRow) * N + bCol);
        __syncthreads();
        #pragma unroll
        for (int k = 0; k < BK; k++) {
            float regM[TM], regN[TN];
            #pragma unroll
            for (int i = 0; i < TM; i++) regM[i] = As[k][tRow + i];
            #pragma unroll
            for (int j = 0; j < TN; j++) regN[j] = Bs[k][tCol + j];
            #pragma unroll
            for (int i = 0; i < TM; i++)
                #pragma unroll
                for (int j = 0; j < TN; j++) acc[i][j] += regM[i] * regN[j];
        }
        __syncthreads();
    }
    #pragma unroll
    for (int i = 0; i < TM; i++) {
        int gr = mtile * BM + tRow + i;
        if (gr >= M) continue;
        float* Cp = C + (size_t)gr * N + (size_t)ntile * BN + tCol;
        const float* Rp = HAS_RES ? (res + (size_t)gr * N + (size_t)ntile * BN + tCol) : nullptr;
        #pragma unroll
        for (int j = 0; j < TN; j++) {
            float v = acc[i][j];
            if (HAS_BIAS) v += bias[(size_t)ntile * BN + tCol + j];
            if (HAS_RES)  v += Rp[j];
            Cp[j] = v;
        }
    }
}

__global__ void __launch_bounds__(256) k_gemm_q(const float* __restrict__ qw,
                                                const float* __restrict__ qb) {
    sgemm_body<true, false>(N_TOK, C_DIM, C_DIM, g_h, qw, qb, nullptr, g_q,
                            blockIdx.y, blockIdx.x);
}
__global__ void __launch_bounds__(256) k_gemm_kv(const float* __restrict__ kvw,
                                                 const float* __restrict__ kvb) {
    sgemm_body<true, false>(N_TOK, 2 * C_DIM, C_DIM, g_h, kvw, kvb, nullptr, g_kv,
                            blockIdx.y, blockIdx.x);
}
__global__ void __launch_bounds__(256) k_gemm_o(const float* __restrict__ ow,
                                                const float* __restrict__ ob,
                                                const float* __restrict__ x) {
    sgemm_body<true, true>(N_TOK, C_DIM, C_DIM, g_y, ow, ob, x, g_x2,
                           blockIdx.y, blockIdx.x);
}

// ---------------- grouped MoE GEMM ----------------
__device__ __forceinline__ void moe_body(const float* __restrict__ Aall,
                                         const float* __restrict__ Ball,
                                         float* __restrict__ Call, int N, int K) {
    int e = blockIdx.z;
    int Me = g_cnt[e];
    int mtile = blockIdx.y;
    if (mtile * 128 >= Me) return;
    int base = g_off[e];
    sgemm_body<false, false>(Me, N, K,
                             Aall + (size_t)base * K,
                             Ball + (size_t)e * K * N,
                             nullptr, nullptr,
                             Call + (size_t)base * N,
                             mtile, blockIdx.x);
}

__global__ void __launch_bounds__(256) k_moe_gate(const float* __restrict__ gw) {
    moe_body(g_xg, gw, g_gate, HID_DIM, C_DIM);
}
__global__ void __launch_bounds__(256) k_moe_up(const float* __restrict__ uw) {
    moe_body(g_xg, uw, g_up, HID_DIM, C_DIM);
}
__global__ void __launch_bounds__(256) k_moe_down(const float* __restrict__ dw) {
    moe_body(g_gate, dw, g_dwn, C_DIM, HID_DIM);
}

// ---------------- attention: flash-style, ALiBi, causal ----------------
__global__ void __launch_bounds__(64) k_attn() {
    const int qt = blockIdx.x;   // query tile (64 queries)
    const int h  = blockIdx.y;
    const int b  = blockIdx.z;
    const int tid = threadIdx.x; // one query row per thread
    __shared__ float Ks[64][64];
    __shared__ float Vs[64][64];
    const int qpos = qt * 64 + tid;
    const float slope = (float)(h + 1) * (1.0f / (float)NH);

    float qreg[HD], o[HD];
    {
        const float* qr = g_q + (size_t)(b * T_SEQ + qpos) * C_DIM + h * HD;
        #pragma unroll
        for (int d = 0; d < HD; d++) { qreg[d] = qr[d] * 0.125f; o[d] = 0.f; }
    }
    float m = -1e30f, l = 0.f;

    for (int kt = 0; kt <= qt; kt++) {
        __syncthreads();
        const float* kb = g_kv + (size_t)(b * T_SEQ + kt * 64) * (2 * C_DIM) + h * HD;
        #pragma unroll 4
        for (int i = 0; i < 64; i++) {
            Ks[i][tid] = kb[(size_t)i * (2 * C_DIM) + tid];
            Vs[i][tid] = kb[(size_t)i * (2 * C_DIM) + C_DIM + tid];
        }
        __syncthreads();
        const int nvalid = (kt < qt) ? 64 : (tid + 1);
        const float bias0 = slope * (float)(kt * 64 - qpos);

        for (int j0 = 0; j0 < nvalid; j0 += 16) {
            float s[16];
            float cmax = -1e30f;
            #pragma unroll
            for (int jj = 0; jj < 16; jj++) {
                int j = j0 + jj;
                float s0 = 0.f, s1 = 0.f, s2 = 0.f, s3 = 0.f;
                #pragma unroll
                for (int d = 0; d < HD; d += 16) {
                    float4 a0 = *(const float4*)&Ks[j][d];
                    float4 a1 = *(const float4*)&Ks[j][d + 4];
                    float4 a2 = *(const float4*)&Ks[j][d + 8];
                    float4 a3 = *(const float4*)&Ks[j][d + 12];
                    s0 += qreg[d+0]*a0.x + qreg[d+1]*a0.y + qreg[d+2]*a0.z + qreg[d+3]*a0.w;
                    s1 += qreg[d+4]*a1.x + qreg[d+5]*a1.y + qreg[d+6]*a1.z + qreg[d+7]*a1.w;
                    s2 += qreg[d+8]*a2.x + qreg[d+9]*a2.y + qreg[d+10]*a2.z + qreg[d+11]*a2.w;
                    s3 += qreg[d+12]*a3.x + qreg[d+13]*a3.y + qreg[d+14]*a3.z + qreg[d+15]*a3.w;
                }
                float v = (s0 + s1) + (s2 + s3) + bias0 + slope * (float)j;
                if (j >= nvalid) v = -1e30f;     // masked: exp() -> 0, Vs row is finite
                s[jj] = v;
                cmax = fmaxf(cmax, v);
            }
            float mnew = fmaxf(m, cmax);
            float corr = __expf(m - mnew);
            m = mnew;
            l *= corr;
            #pragma unroll
            for (int d = 0; d < HD; d++) o[d] *= corr;
            #pragma unroll
            for (int jj = 0; jj < 16; jj++) {
                int j = j0 + jj;
                float p = __expf(s[jj] - m);
                l += p;
                #pragma unroll
                for (int d = 0; d < HD; d += 4) {
                    float4 v4 = *(const float4*)&Vs[j][d];
                    o[d+0] += p * v4.x; o[d+1] += p * v4.y;
                    o[d+2] += p * v4.z; o[d+3] += p * v4.w;
                }
            }
        }
    }
    float inv = 1.f / l;
    float* yr = g_y + (size_t)(b * T_SEQ + qpos) * C_DIM + h * HD;
    #pragma unroll
    for (int d = 0; d < HD; d++) yr[d] = o[d] * inv;
}

// ---------------- router + top-2 ----------------
__global__ void __launch_bounds__(256) k_router(const float* __restrict__ rw) {
    int warp = (blockIdx.x * blockDim.x + threadIdx.x) >> 5;
    int lane = threadIdx.x & 31;
    if (warp >= N_TOK) return;
    float acc[E_NUM];
    #pragma unroll
    for (int e = 0; e < E_NUM; e++) acc[e] = 0.f;
    const float* hr = g_h + (size_t)warp * C_DIM;
    for (int c = lane; c < C_DIM; c += 32) {
        float hv = hr[c];
        #pragma unroll
        for (int e = 0; e < E_NUM; e++) acc[e] += hv * rw[(size_t)c * E_NUM + e];
    }
    #pragma unroll
    for (int e = 0; e < E_NUM; e++)
        #pragma unroll
        for (int o = 16; o; o >>= 1) acc[e] += __shfl_xor_sync(0xffffffffu, acc[e], o);
    if (lane == 0) {
        int i0 = 0; float m0 = acc[0];
        #pragma unroll
        for (int e = 1; e < E_NUM; e++) if (acc[e] > m0) { m0 = acc[e]; i0 = e; }
        int i1 = -1; float m1 = -1e30f;
        #pragma unroll
        for (int e = 0; e < E_NUM; e++)
            if (e != i0 && acc[e] > m1) { m1 = acc[e]; i1 = e; }
        float e1 = __expf(m1 - m0);
        float denom = 1.f + e1;
        g_sel[2 * warp]     = i0;
        g_sel[2 * warp + 1] = i1;
        g_rwt[2 * warp]     = 1.f / denom;
        g_rwt[2 * warp + 1] = e1 / denom;
    }
}

// ---------------- routing bookkeeping ----------------
__global__ void k_zero() {
    if (threadIdx.x < E_NUM) { g_cnt[threadIdx.x] = 0; g_fill[threadIdx.x] = 0; }
}
__global__ void __launch_bounds__(256) k_count() {
    int t = blockIdx.x * blockDim.x + threadIdx.x;
    if (t < N_TOK) {
        atomicAdd(&g_cnt[g_sel[2 * t]], 1);
        atomicAdd(&g_cnt[g_sel[2 * t + 1]], 1);
    }
}
__global__ void k_offsets() {
    int s = 0;
    for (int e = 0; e < E_NUM; e++) { g_off[e] = s; s += g_cnt[e]; }
}
__global__ void __launch_bounds__(256) k_scatter() {
    int t = blockIdx.x * blockDim.x + threadIdx.x;
    if (t < N_TOK) {
        #pragma unroll
        for (int k = 0; k < TOPK; k++) {
            int e = g_sel[2 * t + k];
            int pos = atomicAdd(&g_fill[e], 1);
            int slot = g_off[e] + pos;
            g_tok[slot] = t;
            g_slot[2 * t + k] = slot;
        }
    }
}
__global__ void __launch_bounds__(256) k_gather() {
    int slot = blockIdx.x;
    int t = g_tok[slot];
    const float* src = g_h + (size_t)t * C_DIM;
    float* dst = g_xg + (size_t)slot * C_DIM;
    for (int c = threadIdx.x; c < C_DIM; c += 256) dst[c] = src[c];
}

// ---------------- SiLU(gate) * up ----------------
__global__ void __launch_bounds__(256) k_silu() {
    size_t i = (size_t)blockIdx.x * blockDim.x + threadIdx.x;
    float g = g_gate[i];
    float u = g_up[i];
    g_gate[i] = g / (1.f + __expf(-g)) * u;
}

// ---------------- combine: out = x2 + w0*dwn[s0] + w1*dwn[s1] ----------------
__global__ void __launch_bounds__(256) k_combine(float* __restrict__ out) {
    int t = blockIdx.x;
    int s0 = g_slot[2 * t], s1 = g_slot[2 * t + 1];
    float w0 = g_rwt[2 * t], w1 = g_rwt[2 * t + 1];
    const float* xr = g_x2 + (size_t)t * C_DIM;
    const float* d0 = g_dwn + (size_t)s0 * C_DIM;
    const float* d1 = g_dwn + (size_t)s1 * C_DIM;
    float* op = out + (size_t)t * C_DIM;
    for (int c = threadIdx.x; c < C_DIM; c += 256)
        op[c] = xr[c] + w0 * d0[c] + w1 * d1[c];
}

// ---------------- launch ----------------
extern "C" void kernel_launch(void* const* d_in, const int* in_sizes, int n_in,
                              void* d_out, int out_size) {
    const float* x   = (const float*)d_in[0];
    const float* anw = (const float*)d_in[1];
    const float* fnw = (const float*)d_in[2];
    const float* qw  = (const float*)d_in[3];
    const float* qb  = (const float*)d_in[4];
    const float* kvw = (const float*)d_in[5];
    const float* kvb = (const float*)d_in[6];
    const float* ow  = (const float*)d_in[7];
    const float* ob  = (const float*)d_in[8];
    const float* rw  = (const float*)d_in[9];
    const float* gw  = (const float*)d_in[10];
    const float* uw  = (const float*)d_in[11];
    const float* dw  = (const float*)d_in[12];
    float* out = (float*)d_out;

    // attention path
    k_rms1<<<N_TOK, 256>>>(x, anw);
    k_gemm_q <<<dim3(C_DIM / 128, N_TOK / 128), 256>>>(qw, qb);
    k_gemm_kv<<<dim3(2 * C_DIM / 128, N_TOK / 128), 256>>>(kvw, kvb);
    k_attn<<<dim3(T_SEQ / 64, NH, BATCH), 64>>>();
    k_gemm_o <<<dim3(C_DIM / 128, N_TOK / 128), 256>>>(ow, ob, x);

    // MoE path
    k_rms2<<<N_TOK, 256>>>(fnw);
    k_zero<<<1, 32>>>();
    k_router<<<(N_TOK * 32) / 256, 256>>>(rw);
    k_count<<<N_TOK / 256, 256>>>();
    k_offsets<<<1, 1>>>();
    k_scatter<<<N_TOK / 256, 256>>>();
    k_gather<<<NSLOT, 256>>>();
    k_moe_gate<<<dim3(HID_DIM / 128, NSLOT / 128, E_NUM), 256>>>(gw);
    k_moe_up  <<<dim3(HID_DIM / 128, NSLOT / 128, E_NUM), 256>>>(uw);
    k_silu<<<(NSLOT * HID_DIM) / 256, 256>>>();
    k_moe_down<<<dim3(C_DIM / 128, NSLOT / 128, E_NUM), 256>>>(dw);
    k_combine<<<N_TOK, 256>>>(out);
}